// round 17
// baseline (speedup 1.0000x reference)
#include <cuda_runtime.h>
#include <cuda_fp16.h>
#include <math_constants.h>

#define NN       8192
#define IN_DIM   200
#define DD       64
#define BM       128
#define BN       64
#define NT       256
#define NSPLIT   5
#define STAGES   2
#define HROWS    16
#define NEG_BIG  (-1.0e9f)

// fp16 stage: K 64x64 half (8192B) + V 64x64 half (8192B) + A raw 128x64 int (32768B)
#define KBYTES   8192
#define VBYTES   8192
#define ABYTES   32768
#define SSZ_B    (KBYTES + VBYTES + ABYTES)   // 49152

// h_kernel dynamic smem: W (200*64 f32 = 51200 B) + X rows (16*200 f32 = 12800 B)
#define HSMEM_B  (IN_DIM * DD * 4 + HROWS * IN_DIM * 4)   // 64000

// Scratch (all __device__ globals; no allocations)
__device__ __half   g_Hq[NN * DD];             // Q: [row][qpos(d)]
__device__ __half   g_Hk[NN * DD];             // K: [tile][key][kpos(d,key)]
__device__ __half   g_Hv[NN * DD];             // V: [tile][d][vpos(key,d)]
__device__ float    g_Op[NSPLIT * NN * DD];
__device__ float    g_mp[NSPLIT * NN];
__device__ float    g_lp[NSPLIT * NN];

// ---------------------------------------------------------------------------
__device__ __forceinline__ int perm8(int j) { return ((j & 3) << 1) | (j >> 2); }

__device__ __forceinline__ int qpos(int d) {
    return (d >> 4) * 16 + perm8((d >> 1) & 7) * 2 + (d & 1);
}
__device__ __forceinline__ int kpos(int d, int k) {
    return (((d >> 4) ^ (k & 3)) << 4) + perm8((d >> 1) & 7) * 2 + (d & 1);
}
__device__ __forceinline__ int vpos(int k, int d) {
    return (((k >> 4) ^ (d & 3)) << 4) + perm8((k >> 1) & 7) * 2 + (k & 1);
}

__device__ __forceinline__ unsigned packh2(float lo, float hi) {
    unsigned r;
    asm("cvt.rn.f16x2.f32 %0, %1, %2;" : "=r"(r) : "f"(hi), "f"(lo));
    return r;
}

__device__ __forceinline__ void mma_fp16(float c[4],
                                         unsigned a0, unsigned a1,
                                         unsigned a2, unsigned a3,
                                         unsigned b0, unsigned b1) {
    asm volatile(
        "mma.sync.aligned.m16n8k16.row.col.f32.f16.f16.f32 "
        "{%0,%1,%2,%3}, {%4,%5,%6,%7}, {%8,%9}, {%0,%1,%2,%3};"
        : "+f"(c[0]), "+f"(c[1]), "+f"(c[2]), "+f"(c[3])
        : "r"(a0), "r"(a1), "r"(a2), "r"(a3), "r"(b0), "r"(b1));
}

__device__ __forceinline__ void cpa16(unsigned d, const void* s) {
    asm volatile("cp.async.cg.shared.global [%0], [%1], 16;" :: "r"(d), "l"(s));
}
__device__ __forceinline__ void cpa_commit() {
    asm volatile("cp.async.commit_group;" ::: "memory");
}
template <int N>
__device__ __forceinline__ void cpa_wait() {
    asm volatile("cp.async.wait_group %0;" :: "n"(N) : "memory");
}

// ---------------------------------------------------------------------------
// Kernel 1: H = X @ W + b, fp16-rounded into the three flash layouts.
// W + X rows staged in DYNAMIC smem (64000 B, beyond the 48 KB static cap);
// 16 rows/block, 4 rows/thread (4 independent FMA chains, 4x W amortization).
// ---------------------------------------------------------------------------
__global__ __launch_bounds__(256)
void h_kernel(const float* __restrict__ X,
              const float* __restrict__ W,
              const float* __restrict__ b) {
    extern __shared__ float hsm[];
    float* sW = hsm;                        // [IN_DIM * DD]
    float* sx = hsm + IN_DIM * DD;          // [HROWS * IN_DIM]
    const int tid  = threadIdx.x;
    const int rowq = blockIdx.x * HROWS;

    for (int i = tid; i < IN_DIM * DD / 4; i += 256)
        ((float4*)sW)[i] = ((const float4*)W)[i];
    for (int i = tid; i < HROWS * IN_DIM / 4; i += 256)
        ((float4*)sx)[i] = ((const float4*)(X + (size_t)rowq * IN_DIM))[i];
    __syncthreads();

    const int r = tid >> 6, d = tid & 63;
    float acc[4];
    {
        float bb = b[d];
        acc[0] = bb; acc[1] = bb; acc[2] = bb; acc[3] = bb;
    }
#pragma unroll 8
    for (int k = 0; k < IN_DIM; k++) {
        float wv = sW[k * DD + d];
        acc[0] = fmaf(sx[(r     ) * IN_DIM + k], wv, acc[0]);
        acc[1] = fmaf(sx[(r + 4 ) * IN_DIM + k], wv, acc[1]);
        acc[2] = fmaf(sx[(r + 8 ) * IN_DIM + k], wv, acc[2]);
        acc[3] = fmaf(sx[(r + 12) * IN_DIM + k], wv, acc[3]);
    }
#pragma unroll
    for (int j = 0; j < 4; j++) {
        int    row = rowq + r + 4 * j;
        __half hv  = __float2half_rn(acc[j]);
        int    t   = row >> 6, key = row & 63;
        g_Hq[row * DD + qpos(d)]                      = hv;
        g_Hk[t * (BN * DD) + key * DD + kpos(d, key)] = hv;
        g_Hv[t * (BN * DD) + d * DD + vpos(key, d)]   = hv;
    }
}

// ---------------------------------------------------------------------------
// Kernel 2: split-K flash attention on fp16 m16n8k16. 2-stage cp.async
// pipeline streams K/V AND raw adjacency (A read overlaps compute).
// Grid = 296 = 2x148: q-tiles 0..39 have 5 splits {26,26,26,25,25},
// q-tiles 40..63 have 4 splits {32,32,32,32}.
// ---------------------------------------------------------------------------
__global__ __launch_bounds__(NT, 2)
void flash_mma(const int* __restrict__ A) {
    extern __shared__ char sm[];
    const unsigned smb = (unsigned)__cvta_generic_to_shared(sm);

    const int tid   = threadIdx.x;
    const int lane  = tid & 31;
    const int lr    = lane >> 2;
    const int lrm   = lr & 3;
    const int lc    = lane & 3;
    const int w     = tid >> 5;

    // ---- balanced work-unit decode (partitions [0,128) key tiles) ----
    int qt, si, t0, len;
    {
        const int b = blockIdx.x;
        if (b < 96) {                      // U32: qt 40..63, 4 splits of 32
            qt = 40 + (b >> 2); si = b & 3; t0 = si * 32; len = 32;
        } else if (b < 164) {              // U26 (part): j in [0,52) u [104,120)
            int j = (b < 148) ? (b - 96) : (104 + (b - 148));
            qt = j / 3; si = j % 3; t0 = si * 26; len = 26;
        } else if (b < 244) {              // U25: qt 0..39, splits 3,4
            int k = b - 164;
            qt = k >> 1; si = 3 + (k & 1); t0 = 78 + (k & 1) * 25; len = 25;
        } else {                           // U26 (rest): j in [52,104)
            int j = 52 + (b - 244);
            qt = j / 3; si = j % 3; t0 = si * 26; len = 26;
        }
    }
    const int qbase = qt * BM;
    const int t1    = t0 + len;

    const int lrow0 = w * 16 + lr;
    const int r0    = qbase + lrow0;

    // ---- prologue: issue tiles t0 -> stage0, t0+1 -> stage1 ----
#pragma unroll
    for (int ps = 0; ps < 2; ps++) {
        const unsigned base = smb + ps * SSZ_B;
        const char* gk = (const char*)g_Hk + (size_t)(t0 + ps) * KBYTES;
        const char* gv = (const char*)g_Hv + (size_t)(t0 + ps) * VBYTES;
        cpa16(base + tid * 16,                  gk + tid * 16);
        cpa16(base + (tid + NT) * 16,           gk + (tid + NT) * 16);
        cpa16(base + KBYTES + tid * 16,         gv + tid * 16);
        cpa16(base + KBYTES + (tid + NT) * 16,  gv + (tid + NT) * 16);
#pragma unroll
        for (int ii = 0; ii < 8; ii++) {
            int g = tid + ii * NT;
            int row = g >> 4, c = g & 15;
            cpa16(base + KBYTES + VBYTES + row * 256 + ((c ^ (row & 15)) << 4),
                  A + (size_t)(qbase + row) * NN + (t0 + ps) * BN + c * 4);
        }
        cpa_commit();
    }

    // ---- Q fragments in registers: 16 regs ----
    unsigned aQ[4][4];
#pragma unroll
    for (int ks = 0; ks < 4; ks++) {
        uint2 qa = *(const uint2*)((const char*)g_Hq + ((size_t)r0 * DD + ks * 16 + 4 * lc) * 2);
        uint2 qb = *(const uint2*)((const char*)g_Hq + ((size_t)(r0 + 8) * DD + ks * 16 + 4 * lc) * 2);
        aQ[ks][0] = qa.x;
        aQ[ks][1] = qb.x;
        aQ[ks][2] = qa.y;
        aQ[ks][3] = qb.y;
    }

    float oc[8][4];
#pragma unroll
    for (int na = 0; na < 8; na++)
#pragma unroll
        for (int j = 0; j < 4; j++) oc[na][j] = 0.0f;
    float m0 = -CUDART_INF_F, m1 = -CUDART_INF_F;
    float l0 = 0.0f, l1 = 0.0f;

    for (int t = t0; t < t1; t++) {
        const int s = (t - t0) & 1;

        cpa_wait<1>();       // tile t's group complete
        __syncthreads();     // visible to all threads

        const char* cK = sm + s * SSZ_B;
        const char* cV = cK + KBYTES;
        const int*  cA = (const int*)(cV + VBYTES);

        // ---- S = Q K^T (fp16, 4 k-steps) ----
        float sc[8][4];
#pragma unroll
        for (int na = 0; na < 8; na++)
#pragma unroll
            for (int j = 0; j < 4; j++) sc[na][j] = 0.0f;
#pragma unroll
        for (int ks = 0; ks < 4; ks++) {
#pragma unroll
            for (int na = 0; na < 8; na++) {
                uint2 bk = *(const uint2*)(cK + (((na * 8 + lr) * DD
                              + ((ks ^ lrm) << 4) + 4 * lc) * 2));
                mma_fp16(sc[na], aQ[ks][0], aQ[ks][1], aQ[ks][2], aQ[ks][3],
                         bk.x, bk.y);
            }
        }

        // ---- mask straight from swizzled raw A in smem ----
        {
            const int x0 = lrow0 & 15, x1 = (lrow0 + 8) & 15;
            const int o  = (lc & 1) * 2;
#pragma unroll
            for (int na = 0; na < 8; na++) {
                int c = na * 2 + (lc >> 1);
                int2 a0 = *(const int2*)(cA + lrow0 * 64       + ((c ^ x0) << 2) + o);
                int2 a1 = *(const int2*)(cA + (lrow0 + 8) * 64 + ((c ^ x1) << 2) + o);
                sc[na][0] = (a0.x > 0) ? sc[na][0] : NEG_BIG;
                sc[na][1] = (a0.y > 0) ? sc[na][1] : NEG_BIG;
                sc[na][2] = (a1.x > 0) ? sc[na][2] : NEG_BIG;
                sc[na][3] = (a1.y > 0) ? sc[na][3] : NEG_BIG;
            }
        }

        // ---- online softmax (fp32) ----
        {
            float mt0 = NEG_BIG, mt1 = NEG_BIG;
#pragma unroll
            for (int na = 0; na < 8; na++) {
                mt0 = fmaxf(mt0, fmaxf(sc[na][0], sc[na][1]));
                mt1 = fmaxf(mt1, fmaxf(sc[na][2], sc[na][3]));
            }
            mt0 = fmaxf(mt0, __shfl_xor_sync(0xffffffffu, mt0, 1));
            mt0 = fmaxf(mt0, __shfl_xor_sync(0xffffffffu, mt0, 2));
            mt1 = fmaxf(mt1, __shfl_xor_sync(0xffffffffu, mt1, 1));
            mt1 = fmaxf(mt1, __shfl_xor_sync(0xffffffffu, mt1, 2));

            float mn0 = fmaxf(m0, mt0), mn1 = fmaxf(m1, mt1);
            float scl0 = __expf(m0 - mn0), scl1 = __expf(m1 - mn1);
            m0 = mn0; m1 = mn1;

            float s0 = 0.0f, s1 = 0.0f;
#pragma unroll
            for (int na = 0; na < 8; na++) {
                sc[na][0] = __expf(sc[na][0] - m0);
                sc[na][1] = __expf(sc[na][1] - m0);
                sc[na][2] = __expf(sc[na][2] - m1);
                sc[na][3] = __expf(sc[na][3] - m1);
                s0 += sc[na][0] + sc[na][1];
                s1 += sc[na][2] + sc[na][3];
            }
            s0 += __shfl_xor_sync(0xffffffffu, s0, 1);
            s0 += __shfl_xor_sync(0xffffffffu, s0, 2);
            s1 += __shfl_xor_sync(0xffffffffu, s1, 1);
            s1 += __shfl_xor_sync(0xffffffffu, s1, 2);
            l0 = l0 * scl0 + s0;
            l1 = l1 * scl1 + s1;

#pragma unroll
            for (int na = 0; na < 8; na++) {
                oc[na][0] *= scl0; oc[na][1] *= scl0;
                oc[na][2] *= scl1; oc[na][3] *= scl1;
            }
        }

        // ---- O += P V ----
#pragma unroll
        for (int ks = 0; ks < 4; ks++) {
            unsigned a0 = packh2(sc[2 * ks][0],     sc[2 * ks][1]);
            unsigned a1 = packh2(sc[2 * ks][2],     sc[2 * ks][3]);
            unsigned a2 = packh2(sc[2 * ks + 1][0], sc[2 * ks + 1][1]);
            unsigned a3 = packh2(sc[2 * ks + 1][2], sc[2 * ks + 1][3]);
#pragma unroll
            for (int na = 0; na < 8; na++) {
                uint2 bv = *(const uint2*)(cV + (((na * 8 + lr) * DD
                              + ((ks ^ lrm) << 4) + 4 * lc) * 2));
                mma_fp16(oc[na], a0, a1, a2, a3, bv.x, bv.y);
            }
        }

        __syncthreads();     // all reads of stage s finished

        // ---- refill stage s with tile t+2 ----
        if (t + 2 < t1) {
            const unsigned base = smb + s * SSZ_B;
            const char* gk = (const char*)g_Hk + (size_t)(t + 2) * KBYTES;
            const char* gv = (const char*)g_Hv + (size_t)(t + 2) * VBYTES;
            cpa16(base + tid * 16,                  gk + tid * 16);
            cpa16(base + (tid + NT) * 16,           gk + (tid + NT) * 16);
            cpa16(base + KBYTES + tid * 16,         gv + tid * 16);
            cpa16(base + KBYTES + (tid + NT) * 16,  gv + (tid + NT) * 16);
#pragma unroll
            for (int ii = 0; ii < 8; ii++) {
                int g = tid + ii * NT;
                int row = g >> 4, c = g & 15;
                cpa16(base + KBYTES + VBYTES + row * 256 + ((c ^ (row & 15)) << 4),
                      A + (size_t)(qbase + row) * NN + (t + 2) * BN + c * 4);
            }
        }
        cpa_commit();
    }

    // ---- write partials (plane si) ----
    float* Op = g_Op + (size_t)si * NN * DD;
#pragma unroll
    for (int na = 0; na < 8; na++) {
        int c0 = na * 8 + 2 * lc;
        *(float2*)&Op[(size_t)r0 * DD + c0]       = make_float2(oc[na][0], oc[na][1]);
        *(float2*)&Op[(size_t)(r0 + 8) * DD + c0] = make_float2(oc[na][2], oc[na][3]);
    }
    if (lc == 0) {
        g_mp[si * NN + r0]     = m0;
        g_mp[si * NN + r0 + 8] = m1;
        g_lp[si * NN + r0]     = l0;
        g_lp[si * NN + r0 + 8] = l1;
    }
}

// ---------------------------------------------------------------------------
// Kernel 3: m-aware merge, all loads batched upfront (MLP). Missing plane 4
// (rows >= 5120) substitutes mp=-inf, lp=0, O=0 -> exact 5-way combine.
// ---------------------------------------------------------------------------
__global__ void merge_kernel(float* __restrict__ Out) {
    int i4  = blockIdx.x * 256 + threadIdx.x;
    int idx = i4 * 4;
    int row = idx >> 6;
    const bool five = (row < 5120);

    float4 o4[NSPLIT];
    float  mpv[NSPLIT], lpv[NSPLIT];
#pragma unroll
    for (int s = 0; s < 4; s++) {
        o4[s]  = *(const float4*)&g_Op[(size_t)s * NN * DD + idx];
        mpv[s] = g_mp[s * NN + row];
        lpv[s] = g_lp[s * NN + row];
    }
    if (five) {
        o4[4]  = *(const float4*)&g_Op[(size_t)4 * NN * DD + idx];
        mpv[4] = g_mp[4 * NN + row];
        lpv[4] = g_lp[4 * NN + row];
    } else {
        o4[4]  = make_float4(0.0f, 0.0f, 0.0f, 0.0f);
        mpv[4] = -CUDART_INF_F;
        lpv[4] = 0.0f;
    }

    float M = mpv[0];
#pragma unroll
    for (int s = 1; s < NSPLIT; s++) M = fmaxf(M, mpv[s]);

    float denom = 0.0f, ax = 0.0f, ay = 0.0f, az = 0.0f, aw = 0.0f;
#pragma unroll
    for (int s = 0; s < NSPLIT; s++) {
        float wgt = __expf(mpv[s] - M);
        denom += wgt * lpv[s];
        ax += wgt * o4[s].x; ay += wgt * o4[s].y;
        az += wgt * o4[s].z; aw += wgt * o4[s].w;
    }
    float inv = 1.0f / denom;
    float4 o;
    o.x = fmaxf(ax * inv, 0.0f);
    o.y = fmaxf(ay * inv, 0.0f);
    o.z = fmaxf(az * inv, 0.0f);
    o.w = fmaxf(aw * inv, 0.0f);
    *(float4*)&Out[idx] = o;
}

// ---------------------------------------------------------------------------
extern "C" void kernel_launch(void* const* d_in, const int* in_sizes, int n_in,
                              void* d_out, int out_size) {
    const float* X = (const float*)d_in[0];
    const int*   A = (const int*)  d_in[1];
    const float* W = (const float*)d_in[2];
    const float* b = (const float*)d_in[3];
    float* Out = (float*)d_out;

    const int smem_bytes = STAGES * SSZ_B;        // 98304
    static bool attr_set = false;
    if (!attr_set) {
        cudaFuncSetAttribute(flash_mma,
                             cudaFuncAttributeMaxDynamicSharedMemorySize,
                             smem_bytes);
        cudaFuncSetAttribute(h_kernel,
                             cudaFuncAttributeMaxDynamicSharedMemorySize,
                             HSMEM_B);
        attr_set = true;
    }

    h_kernel<<<NN / HROWS, 256, HSMEM_B>>>(X, W, b);
    flash_mma<<<296, NT, smem_bytes>>>(A);
    merge_kernel<<<NN * DD / 4 / 256, 256>>>(Out);
}